// round 5
// baseline (speedup 1.0000x reference)
#include <cuda_runtime.h>
#include <cuda_bf16.h>
#include <cstdint>
#include <math.h>

// ===========================================================================
// DynamicMemoryBank — R5: flash attention + fused reductions
//   convert_x: x -> cat fp32 / xb bf16 / catb bf16  + xmean accumulation
//   flash:  retrieved = softmax(x@mem^T)@mem -> cat fp32 + catb bf16
//   G3: h = silu(catb @ w1T^T + b1) -> bf16
//   G4: g = sigmoid(hb @ w2T^T + b2) -> fused newmem atomicAdd (no gate buf)
// ===========================================================================

__device__ __forceinline__ uint32_t smem_u32(const void* p) {
    uint32_t a;
    asm("{ .reg .u64 t; cvta.to.shared.u64 t, %1; cvt.u32.u64 %0, t; }" : "=r"(a) : "l"(p));
    return a;
}

#define LDSM_X4(R0, R1, R2, R3, ADDR) \
    asm volatile("ldmatrix.sync.aligned.m8n8.x4.shared.b16 {%0,%1,%2,%3}, [%4];" \
        : "=r"(R0), "=r"(R1), "=r"(R2), "=r"(R3) : "r"(ADDR))

#define LDSM_X4T(R0, R1, R2, R3, ADDR) \
    asm volatile("ldmatrix.sync.aligned.m8n8.x4.trans.shared.b16 {%0,%1,%2,%3}, [%4];" \
        : "=r"(R0), "=r"(R1), "=r"(R2), "=r"(R3) : "r"(ADDR))

#define MMA16816(C, A0, A1, A2, A3, B0, B1) \
    asm volatile("mma.sync.aligned.m16n8k16.row.col.f32.bf16.bf16.f32 " \
        "{%0,%1,%2,%3}, {%4,%5,%6,%7}, {%8,%9}, {%0,%1,%2,%3};" \
        : "+f"((C)[0]), "+f"((C)[1]), "+f"((C)[2]), "+f"((C)[3]) \
        : "r"(A0), "r"(A1), "r"(A2), "r"(A3), "r"(B0), "r"(B1))

#define CP_ASYNC16(DST, SRC) \
    asm volatile("cp.async.cg.shared.global [%0], [%1], 16;" :: "r"(DST), "l"(SRC))
#define CP_COMMIT() asm volatile("cp.async.commit_group;" ::: "memory")
#define CP_WAIT(N)  asm volatile("cp.async.wait_group %0;" :: "n"(N) : "memory")

// ---------------------------------------------------------------------------
// scratch
// ---------------------------------------------------------------------------
__device__ __nv_bfloat16 g_xb[16777216];      // [65536,256]
__device__ __nv_bfloat16 g_catb[33554432];    // [65536,512]
__device__ __nv_bfloat16 g_hb[67108864];      // [65536,1024]
__device__ __nv_bfloat16 g_memb[262144];      // [1024,256]
__device__ __nv_bfloat16 g_w1T[524288];       // [1024,512]
__device__ __nv_bfloat16 g_w2T[262144];       // [256,1024]
__device__ float         g_xmean[16384];      // [64,256] accumulator

// swizzled addr within a 128-row x 512B tile
__device__ __forceinline__ uint32_t tile_addr(uint32_t base, int r, int colbyte) {
    return base + (uint32_t)(r * 512) + (uint32_t)(colbyte & ~127)
         + (uint32_t)(((((colbyte >> 4) & 7) ^ (r & 7)) << 4));
}

// ---------------------------------------------------------------------------
// zero the atomic accumulators (runs first every replay)
// ---------------------------------------------------------------------------
__global__ void zero_acc(float* __restrict__ nm, float* __restrict__ xm)
{
    int i = blockIdx.x * 256 + threadIdx.x;   // grid 1024 -> 262144
    nm[i] = 0.0f;
    if (i < 16384) xm[i] = 0.0f;
}

// ---------------------------------------------------------------------------
// Flash kernel (as R4): per CTA 128 rows of x; 8 chunks of 128 mem rows.
// ---------------------------------------------------------------------------
__global__ void __launch_bounds__(256, 1)
flash_attn(const __nv_bfloat16* __restrict__ xb, const __nv_bfloat16* __restrict__ memb,
           float* __restrict__ cat, __nv_bfloat16* __restrict__ catb)
{
    extern __shared__ char dsm[];
    const uint32_t sbase = (smem_u32(dsm) + 1023) & ~1023u;
    const uint32_t xs = sbase;
    const uint32_t ms[2] = { sbase + 65536, sbase + 131072 };

    const int tid = threadIdx.x;
    const int wid = tid >> 5, lane = tid & 31;
    const long row0 = (long)blockIdx.x * 128;

    {
        const char* Xg = (const char*)(xb + row0 * 256);
#pragma unroll
        for (int j = 0; j < 16; j++) {
            int idx = tid + j * 256;
            int r = idx >> 5;
            int colbyte = (idx & 31) << 4;
            CP_ASYNC16(tile_addr(xs, r, colbyte), Xg + (long)r * 512 + colbyte);
        }
        CP_COMMIT();
    }
    {
        const char* Mg = (const char*)memb;
#pragma unroll
        for (int j = 0; j < 16; j++) {
            int idx = tid + j * 256;
            int r = idx >> 5;
            int colbyte = (idx & 31) << 4;
            CP_ASYNC16(tile_addr(ms[0], r, colbyte), Mg + (long)r * 512 + colbyte);
        }
        CP_COMMIT();
    }

    float acc_o[32][4];
#pragma unroll
    for (int b = 0; b < 32; b++)
#pragma unroll
        for (int q = 0; q < 4; q++) acc_o[b][q] = 0.0f;
    float m0 = -1e30f, m1 = -1e30f, l0 = 0.0f, l1 = 0.0f;

    for (int c = 0; c < 8; c++) {
        const int b = c & 1;
        if (c + 1 < 8) {
            const char* Mg = (const char*)(memb + (long)(c + 1) * 128 * 256);
#pragma unroll
            for (int j = 0; j < 16; j++) {
                int idx = tid + j * 256;
                int r = idx >> 5;
                int colbyte = (idx & 31) << 4;
                CP_ASYNC16(tile_addr(ms[1 - b], r, colbyte), Mg + (long)r * 512 + colbyte);
            }
            CP_COMMIT();
            CP_WAIT(1);
        } else {
            CP_WAIT(0);
        }
        __syncthreads();

        float acc_s[16][4];
#pragma unroll
        for (int nb = 0; nb < 16; nb++)
#pragma unroll
            for (int q = 0; q < 4; q++) acc_s[nb][q] = 0.0f;

#pragma unroll
        for (int ks = 0; ks < 16; ks++) {
            uint32_t a0, a1, a2, a3;
            {
                int r = 16 * wid + (lane & 15);
                int colbyte = ks * 32 + ((lane >> 4) << 4);
                LDSM_X4(a0, a1, a2, a3, tile_addr(xs, r, colbyte));
            }
#pragma unroll
            for (int nb2 = 0; nb2 < 8; nb2++) {
                uint32_t d0, d1, d2, d3;
                int rn = nb2 * 16 + (lane & 7) + ((lane >> 4) << 3);
                int colbyte = ks * 32 + (((lane >> 3) & 1) << 4);
                LDSM_X4(d0, d1, d2, d3, tile_addr(ms[b], rn, colbyte));
                MMA16816(acc_s[nb2 * 2],     a0, a1, a2, a3, d0, d1);
                MMA16816(acc_s[nb2 * 2 + 1], a0, a1, a2, a3, d2, d3);
            }
        }

        float rm0 = -1e30f, rm1 = -1e30f;
#pragma unroll
        for (int nb = 0; nb < 16; nb++) {
            rm0 = fmaxf(rm0, fmaxf(acc_s[nb][0], acc_s[nb][1]));
            rm1 = fmaxf(rm1, fmaxf(acc_s[nb][2], acc_s[nb][3]));
        }
        rm0 = fmaxf(rm0, __shfl_xor_sync(0xffffffffu, rm0, 1));
        rm0 = fmaxf(rm0, __shfl_xor_sync(0xffffffffu, rm0, 2));
        rm1 = fmaxf(rm1, __shfl_xor_sync(0xffffffffu, rm1, 1));
        rm1 = fmaxf(rm1, __shfl_xor_sync(0xffffffffu, rm1, 2));

        float mn0 = fmaxf(m0, rm0), mn1 = fmaxf(m1, rm1);
        float sc0 = __expf(m0 - mn0), sc1 = __expf(m1 - mn1);
        m0 = mn0; m1 = mn1;

        uint32_t pk[16], qk[16];
        float ls0 = 0.0f, ls1 = 0.0f;
#pragma unroll
        for (int nb = 0; nb < 16; nb++) {
            float e0 = __expf(acc_s[nb][0] - mn0);
            float e1 = __expf(acc_s[nb][1] - mn0);
            float e2 = __expf(acc_s[nb][2] - mn1);
            float e3 = __expf(acc_s[nb][3] - mn1);
            ls0 += e0 + e1; ls1 += e2 + e3;
            __nv_bfloat162 h0 = __float22bfloat162_rn(make_float2(e0, e1));
            __nv_bfloat162 h1 = __float22bfloat162_rn(make_float2(e2, e3));
            pk[nb] = *reinterpret_cast<uint32_t*>(&h0);
            qk[nb] = *reinterpret_cast<uint32_t*>(&h1);
        }
        ls0 += __shfl_xor_sync(0xffffffffu, ls0, 1);
        ls0 += __shfl_xor_sync(0xffffffffu, ls0, 2);
        ls1 += __shfl_xor_sync(0xffffffffu, ls1, 1);
        ls1 += __shfl_xor_sync(0xffffffffu, ls1, 2);
        l0 = l0 * sc0 + ls0;
        l1 = l1 * sc1 + ls1;

#pragma unroll
        for (int nb = 0; nb < 32; nb++) {
            acc_o[nb][0] *= sc0; acc_o[nb][1] *= sc0;
            acc_o[nb][2] *= sc1; acc_o[nb][3] *= sc1;
        }

#pragma unroll
        for (int j = 0; j < 8; j++) {
            uint32_t a0 = pk[2 * j], a1 = qk[2 * j], a2 = pk[2 * j + 1], a3 = qk[2 * j + 1];
#pragma unroll
            for (int on = 0; on < 16; on++) {
                uint32_t d0, d1, d2, d3;
                int grp = lane >> 3;
                int rv = 16 * j + ((grp & 1) << 3) + (lane & 7);
                int colbyte = on * 32 + ((grp >> 1) << 4);
                LDSM_X4T(d0, d1, d2, d3, tile_addr(ms[b], rv, colbyte));
                MMA16816(acc_o[on * 2],     a0, a1, a2, a3, d0, d1);
                MMA16816(acc_o[on * 2 + 1], a0, a1, a2, a3, d2, d3);
            }
        }
        __syncthreads();
    }

    float inv0 = 1.0f / l0, inv1 = 1.0f / l1;
    long r0 = row0 + 16 * wid + (lane >> 2);
    long r1 = r0 + 8;
#pragma unroll
    for (int nb = 0; nb < 32; nb++) {
        int cn = 256 + nb * 8 + (lane & 3) * 2;
        float v0 = acc_o[nb][0] * inv0, v1 = acc_o[nb][1] * inv0;
        float v2 = acc_o[nb][2] * inv1, v3 = acc_o[nb][3] * inv1;
        *(float2*)(cat + r0 * 512 + cn) = make_float2(v0, v1);
        *(float2*)(cat + r1 * 512 + cn) = make_float2(v2, v3);
        __nv_bfloat162 h0 = __float22bfloat162_rn(make_float2(v0, v1));
        __nv_bfloat162 h1 = __float22bfloat162_rn(make_float2(v2, v3));
        *(uint32_t*)(catb + r0 * 512 + cn) = *reinterpret_cast<uint32_t*>(&h0);
        *(uint32_t*)(catb + r1 * 512 + cn) = *reinterpret_cast<uint32_t*>(&h1);
    }
}

// ---------------------------------------------------------------------------
// bf16 GEMM: BM=128, BN=128, BK=64, 256 thr, warp tile 32x64.
// EPI 2: h = silu(v+bias) -> bf16 Cb
// EPI 3: g = sigmoid(v+bias); newmem atomicAdd (no gate buffer)
// ---------------------------------------------------------------------------
template<int EPI>
__global__ void __launch_bounds__(256, 2)
gemm_mma(const __nv_bfloat16* __restrict__ A, const __nv_bfloat16* __restrict__ B,
         const float* __restrict__ bias, __nv_bfloat16* __restrict__ Cb,
         int K, int ldcb, int c_off,
         const float* __restrict__ mem, const float* __restrict__ xm,
         float* __restrict__ nm)
{
    extern __shared__ char dsm[];
    const uint32_t sbase = (smem_u32(dsm) + 1023) & ~1023u;
    const int tid = threadIdx.x;
    const int wid = tid >> 5, lane = tid & 31;
    const int wm = wid & 3;
    const int wn = wid >> 2;
    const long row0 = (long)blockIdx.y * 128;
    const long col0 = (long)blockIdx.x * 128;

    const uint32_t sA[2] = { sbase,         sbase + 32768 };
    const uint32_t sB[2] = { sbase + 16384, sbase + 49152 };

    float acc[2][8][4];
#pragma unroll
    for (int i = 0; i < 2; i++)
#pragma unroll
        for (int j = 0; j < 8; j++)
#pragma unroll
            for (int q = 0; q < 4; q++) acc[i][j][q] = 0.0f;

    const char* Ag = (const char*)(A + row0 * K);
    const char* Bg = (const char*)(B + col0 * K);
    const long rowb = (long)K * 2;
    const int lr = tid >> 3;
    const int lc = tid & 7;
    const int nchunks = K >> 6;

    {
#pragma unroll
        for (int j = 0; j < 4; j++) {
            int r = lr + j * 32;
            uint32_t off = (uint32_t)(r * 128) + (uint32_t)((lc ^ (r & 7)) << 4);
            CP_ASYNC16(sA[0] + off, Ag + (long)r * rowb + lc * 16);
            CP_ASYNC16(sB[0] + off, Bg + (long)r * rowb + lc * 16);
        }
        CP_COMMIT();
    }

    for (int i = 0; i < nchunks; i++) {
        const int b = i & 1;
        if (i + 1 < nchunks) {
            const long kb = (long)(i + 1) << 7;
#pragma unroll
            for (int j = 0; j < 4; j++) {
                int r = lr + j * 32;
                uint32_t off = (uint32_t)(r * 128) + (uint32_t)((lc ^ (r & 7)) << 4);
                CP_ASYNC16(sA[1 - b] + off, Ag + (long)r * rowb + kb + lc * 16);
                CP_ASYNC16(sB[1 - b] + off, Bg + (long)r * rowb + kb + lc * 16);
            }
            CP_COMMIT();
            CP_WAIT(1);
        } else {
            CP_WAIT(0);
        }
        __syncthreads();

#pragma unroll
        for (int ks = 0; ks < 4; ks++) {
            uint32_t af[2][4];
#pragma unroll
            for (int mi = 0; mi < 2; mi++) {
                int r = wm * 32 + mi * 16 + (lane & 15);
                int cch = ks * 2 + (lane >> 4);
                uint32_t addr = sA[b] + (uint32_t)(r * 128) + (uint32_t)((cch ^ (r & 7)) << 4);
                LDSM_X4(af[mi][0], af[mi][1], af[mi][2], af[mi][3], addr);
            }
            uint32_t bf[4][4];
#pragma unroll
            for (int nt = 0; nt < 4; nt++) {
                int r = wn * 64 + nt * 16 + (lane & 7) + ((lane >> 4) << 3);
                int cch = ks * 2 + ((lane >> 3) & 1);
                uint32_t addr = sB[b] + (uint32_t)(r * 128) + (uint32_t)((cch ^ (r & 7)) << 4);
                LDSM_X4(bf[nt][0], bf[nt][1], bf[nt][2], bf[nt][3], addr);
            }
#pragma unroll
            for (int mi = 0; mi < 2; mi++)
#pragma unroll
                for (int ni = 0; ni < 8; ni++) {
                    uint32_t b0 = bf[ni >> 1][(ni & 1) * 2];
                    uint32_t b1 = bf[ni >> 1][(ni & 1) * 2 + 1];
                    MMA16816(acc[mi][ni], af[mi][0], af[mi][1], af[mi][2], af[mi][3], b0, b1);
                }
        }
        __syncthreads();
    }

#pragma unroll
    for (int mi = 0; mi < 2; mi++) {
#pragma unroll
        for (int h = 0; h < 2; h++) {
            long r = row0 + wm * 32 + mi * 16 + (lane >> 2) + h * 8;
#pragma unroll
            for (int ni = 0; ni < 8; ni++) {
                int cn = (int)col0 + wn * 64 + ni * 8 + (lane & 3) * 2;
                float v0 = acc[mi][ni][h * 2]     + bias[cn];
                float v1 = acc[mi][ni][h * 2 + 1] + bias[cn + 1];
                if (EPI == 2) {
                    v0 = v0 / (1.0f + __expf(-v0));
                    v1 = v1 / (1.0f + __expf(-v1));
                    __nv_bfloat162 h2 = __float22bfloat162_rn(make_float2(v0, v1));
                    *(uint32_t*)(Cb + r * ldcb + c_off + cn) = *reinterpret_cast<uint32_t*>(&h2);
                } else {
                    float g0 = 1.0f / (1.0f + __expf(-v0));
                    float g1 = 1.0f / (1.0f + __expf(-v1));
                    int bb = (int)(r >> 10);
                    int m  = (int)(r & 1023);
                    float mm0 = mem[m * 256 + cn],     mm1 = mem[m * 256 + cn + 1];
                    float xv0 = xm[bb * 256 + cn],     xv1 = xm[bb * 256 + cn + 1];
                    float o0 = fmaf(xv0 - mm0, g0, mm0) * (1.0f / 64.0f);
                    float o1 = fmaf(xv1 - mm1, g1, mm1) * (1.0f / 64.0f);
                    atomicAdd(nm + m * 256 + cn,     o0);
                    atomicAdd(nm + m * 256 + cn + 1, o1);
                }
            }
        }
    }
}

// ---------------------------------------------------------------------------
// convert_x + xmean accumulation.
// Block covers 4 consecutive rows (same b). smem column-reduce, then atomics.
// ---------------------------------------------------------------------------
__global__ void convert_x(const float4* __restrict__ x4, float4* __restrict__ cat4,
                          uint2* __restrict__ xb2, uint2* __restrict__ catb2,
                          float* __restrict__ xm)
{
    __shared__ float4 red[256];
    const int tid = threadIdx.x;
    long i = (long)blockIdx.x * 256 + tid;
    long row = i >> 6;
    long c4 = i & 63;
    float4 v = x4[i];
    cat4[row * 128 + c4] = v;
    __nv_bfloat162 l = __float22bfloat162_rn(make_float2(v.x, v.y));
    __nv_bfloat162 h = __float22bfloat162_rn(make_float2(v.z, v.w));
    uint2 pk = make_uint2(*reinterpret_cast<uint32_t*>(&l), *reinterpret_cast<uint32_t*>(&h));
    xb2[i] = pk;
    catb2[row * 128 + c4] = pk;

    red[tid] = v;
    __syncthreads();
    if (tid < 64) {
        float4 s0 = red[tid], s1 = red[tid + 64], s2 = red[tid + 128], s3 = red[tid + 192];
        const float inv = 1.0f / 1024.0f;
        float sx = (s0.x + s1.x + s2.x + s3.x) * inv;
        float sy = (s0.y + s1.y + s2.y + s3.y) * inv;
        float sz = (s0.z + s1.z + s2.z + s3.z) * inv;
        float sw = (s0.w + s1.w + s2.w + s3.w) * inv;
        int b = (int)((blockIdx.x * 4) >> 10);
        float* dst = xm + b * 256 + tid * 4;
        atomicAdd(dst,     sx);
        atomicAdd(dst + 1, sy);
        atomicAdd(dst + 2, sz);
        atomicAdd(dst + 3, sw);
    }
}

// ---------------------------------------------------------------------------
__global__ void conv_mem(const float* __restrict__ mem, __nv_bfloat16* __restrict__ memb)
{
    int i = blockIdx.x * 256 + threadIdx.x;
    memb[i] = __float2bfloat16(mem[i]);
}

__global__ void conv_w1(const float* __restrict__ w1, __nv_bfloat16* __restrict__ w1T)
{
    int i = blockIdx.x * 256 + threadIdx.x;
    int k = i >> 10, n = i & 1023;
    w1T[n * 512 + k] = __float2bfloat16(w1[i]);
}

__global__ void conv_w2(const float* __restrict__ w2, __nv_bfloat16* __restrict__ w2T)
{
    int i = blockIdx.x * 256 + threadIdx.x;
    int f = i >> 8, c = i & 255;
    w2T[c * 1024 + f] = __float2bfloat16(w2[i]);
}

// ---------------------------------------------------------------------------
extern "C" void kernel_launch(void* const* d_in, const int* in_sizes, int n_in,
                              void* d_out, int out_size)
{
    const float* x      = (const float*)d_in[0];
    const float* memory = (const float*)d_in[1];
    const float* w1     = (const float*)d_in[2];
    const float* b1     = (const float*)d_in[3];
    const float* w2     = (const float*)d_in[4];
    const float* b2     = (const float*)d_in[5];

    float* out    = (float*)d_out;
    float* cat    = out;               // [65536,512]
    float* newmem = out + 33554432ll;  // [1024,256]

    __nv_bfloat16 *xb, *catb, *hb, *memb, *w1T, *w2T;
    float *xm;
    cudaGetSymbolAddress((void**)&xb, g_xb);
    cudaGetSymbolAddress((void**)&catb, g_catb);
    cudaGetSymbolAddress((void**)&hb, g_hb);
    cudaGetSymbolAddress((void**)&memb, g_memb);
    cudaGetSymbolAddress((void**)&w1T, g_w1T);
    cudaGetSymbolAddress((void**)&w2T, g_w2T);
    cudaGetSymbolAddress((void**)&xm, g_xmean);

    const int SMEM_G = 1024 + 65536;          // gemm: guard + 2x(16KB+16KB)
    const int SMEM_F = 1024 + 3 * 65536;      // flash: guard + x + 2 mem bufs
    cudaFuncSetAttribute(gemm_mma<2>, cudaFuncAttributeMaxDynamicSharedMemorySize, SMEM_G);
    cudaFuncSetAttribute(gemm_mma<3>, cudaFuncAttributeMaxDynamicSharedMemorySize, SMEM_G);
    cudaFuncSetAttribute(flash_attn, cudaFuncAttributeMaxDynamicSharedMemorySize, SMEM_F);

    // zero accumulators (must precede convert_x and G4 each replay)
    zero_acc<<<1024, 256>>>(newmem, xm);

    // conversions + xmean accumulation
    convert_x<<<16384, 256>>>((const float4*)x, (float4*)cat, (uint2*)xb, (uint2*)catb, xm);
    conv_mem<<<1024, 256>>>(memory, memb);
    conv_w1<<<2048, 256>>>(w1, w1T);
    conv_w2<<<1024, 256>>>(w2, w2T);

    // fused G1 + softmax + G2 -> cat[:,256:512] fp32 + catb[:,256:512] bf16
    flash_attn<<<512, 256, SMEM_F>>>(xb, memb, cat, catb);

    // G3: h = silu(catb @ w1T^T + b1) -> hb bf16 [65536,1024]
    gemm_mma<2><<<dim3(8, 512), 256, SMEM_G>>>(catb, w1T, b1, hb, 512, 1024, 0,
                                               nullptr, nullptr, nullptr);

    // G4: g = sigmoid(hb @ w2T^T + b2), fused newmem reduction (atomics)
    gemm_mma<3><<<dim3(2, 512), 256, SMEM_G>>>(hb, w2T, b2, nullptr, 1024, 0, 0,
                                               memory, xm, newmem);
}

// round 8
// speedup vs baseline: 1.0992x; 1.0992x over previous
#include <cuda_runtime.h>
#include <cuda_bf16.h>
#include <cstdint>
#include <math.h>

// ===========================================================================
// DynamicMemoryBank — R6: R4 pipeline + atomic-free fused reductions
//   convert_x: x -> cat fp32 / xb bf16 / catb bf16
//   xmean: 2-stage parallel (no atomics)
//   flash:  retrieved = softmax(x@mem^T)@mem -> cat fp32 + catb bf16
//   G3: h = silu(catb @ w1T^T + b1) -> bf16
//   G4: g = sigmoid(hb @ w2T^T + b2), CTA rows = 64 b x 2 m,
//       in-CTA reduce over b -> newmem direct store (no gate buffer)
// ===========================================================================

__device__ __forceinline__ uint32_t smem_u32(const void* p) {
    uint32_t a;
    asm("{ .reg .u64 t; cvta.to.shared.u64 t, %1; cvt.u32.u64 %0, t; }" : "=r"(a) : "l"(p));
    return a;
}

#define LDSM_X4(R0, R1, R2, R3, ADDR) \
    asm volatile("ldmatrix.sync.aligned.m8n8.x4.shared.b16 {%0,%1,%2,%3}, [%4];" \
        : "=r"(R0), "=r"(R1), "=r"(R2), "=r"(R3) : "r"(ADDR))

#define LDSM_X4T(R0, R1, R2, R3, ADDR) \
    asm volatile("ldmatrix.sync.aligned.m8n8.x4.trans.shared.b16 {%0,%1,%2,%3}, [%4];" \
        : "=r"(R0), "=r"(R1), "=r"(R2), "=r"(R3) : "r"(ADDR))

#define MMA16816(C, A0, A1, A2, A3, B0, B1) \
    asm volatile("mma.sync.aligned.m16n8k16.row.col.f32.bf16.bf16.f32 " \
        "{%0,%1,%2,%3}, {%4,%5,%6,%7}, {%8,%9}, {%0,%1,%2,%3};" \
        : "+f"((C)[0]), "+f"((C)[1]), "+f"((C)[2]), "+f"((C)[3]) \
        : "r"(A0), "r"(A1), "r"(A2), "r"(A3), "r"(B0), "r"(B1))

#define CP_ASYNC16(DST, SRC) \
    asm volatile("cp.async.cg.shared.global [%0], [%1], 16;" :: "r"(DST), "l"(SRC))
#define CP_COMMIT() asm volatile("cp.async.commit_group;" ::: "memory")
#define CP_WAIT(N)  asm volatile("cp.async.wait_group %0;" :: "n"(N) : "memory")

// ---------------------------------------------------------------------------
// scratch
// ---------------------------------------------------------------------------
__device__ __nv_bfloat16 g_xb[16777216];      // [65536,256]
__device__ __nv_bfloat16 g_catb[33554432];    // [65536,512]
__device__ __nv_bfloat16 g_hb[67108864];      // [65536,1024]
__device__ __nv_bfloat16 g_memb[262144];      // [1024,256]
__device__ __nv_bfloat16 g_w1T[524288];       // [1024,512]
__device__ __nv_bfloat16 g_w2T[262144];       // [256,1024]
__device__ float         g_xpart[131072];     // [512,256] xmean partials
__device__ float         g_xmean[16384];      // [64,256]

// swizzled addr within a 128-row x 512B tile
__device__ __forceinline__ uint32_t tile_addr(uint32_t base, int r, int colbyte) {
    return base + (uint32_t)(r * 512) + (uint32_t)(colbyte & ~127)
         + (uint32_t)(((((colbyte >> 4) & 7) ^ (r & 7)) << 4));
}

// ---------------------------------------------------------------------------
// Flash kernel (as R4): per CTA 128 rows of x; 8 chunks of 128 mem rows.
// ---------------------------------------------------------------------------
__global__ void __launch_bounds__(256, 1)
flash_attn(const __nv_bfloat16* __restrict__ xb, const __nv_bfloat16* __restrict__ memb,
           float* __restrict__ cat, __nv_bfloat16* __restrict__ catb)
{
    extern __shared__ char dsm[];
    const uint32_t sbase = (smem_u32(dsm) + 1023) & ~1023u;
    const uint32_t xs = sbase;
    const uint32_t ms[2] = { sbase + 65536, sbase + 131072 };

    const int tid = threadIdx.x;
    const int wid = tid >> 5, lane = tid & 31;
    const long row0 = (long)blockIdx.x * 128;

    {
        const char* Xg = (const char*)(xb + row0 * 256);
#pragma unroll
        for (int j = 0; j < 16; j++) {
            int idx = tid + j * 256;
            int r = idx >> 5;
            int colbyte = (idx & 31) << 4;
            CP_ASYNC16(tile_addr(xs, r, colbyte), Xg + (long)r * 512 + colbyte);
        }
        CP_COMMIT();
    }
    {
        const char* Mg = (const char*)memb;
#pragma unroll
        for (int j = 0; j < 16; j++) {
            int idx = tid + j * 256;
            int r = idx >> 5;
            int colbyte = (idx & 31) << 4;
            CP_ASYNC16(tile_addr(ms[0], r, colbyte), Mg + (long)r * 512 + colbyte);
        }
        CP_COMMIT();
    }

    float acc_o[32][4];
#pragma unroll
    for (int b = 0; b < 32; b++)
#pragma unroll
        for (int q = 0; q < 4; q++) acc_o[b][q] = 0.0f;
    float m0 = -1e30f, m1 = -1e30f, l0 = 0.0f, l1 = 0.0f;

    for (int c = 0; c < 8; c++) {
        const int b = c & 1;
        if (c + 1 < 8) {
            const char* Mg = (const char*)(memb + (long)(c + 1) * 128 * 256);
#pragma unroll
            for (int j = 0; j < 16; j++) {
                int idx = tid + j * 256;
                int r = idx >> 5;
                int colbyte = (idx & 31) << 4;
                CP_ASYNC16(tile_addr(ms[1 - b], r, colbyte), Mg + (long)r * 512 + colbyte);
            }
            CP_COMMIT();
            CP_WAIT(1);
        } else {
            CP_WAIT(0);
        }
        __syncthreads();

        float acc_s[16][4];
#pragma unroll
        for (int nb = 0; nb < 16; nb++)
#pragma unroll
            for (int q = 0; q < 4; q++) acc_s[nb][q] = 0.0f;

#pragma unroll
        for (int ks = 0; ks < 16; ks++) {
            uint32_t a0, a1, a2, a3;
            {
                int r = 16 * wid + (lane & 15);
                int colbyte = ks * 32 + ((lane >> 4) << 4);
                LDSM_X4(a0, a1, a2, a3, tile_addr(xs, r, colbyte));
            }
#pragma unroll
            for (int nb2 = 0; nb2 < 8; nb2++) {
                uint32_t d0, d1, d2, d3;
                int rn = nb2 * 16 + (lane & 7) + ((lane >> 4) << 3);
                int colbyte = ks * 32 + (((lane >> 3) & 1) << 4);
                LDSM_X4(d0, d1, d2, d3, tile_addr(ms[b], rn, colbyte));
                MMA16816(acc_s[nb2 * 2],     a0, a1, a2, a3, d0, d1);
                MMA16816(acc_s[nb2 * 2 + 1], a0, a1, a2, a3, d2, d3);
            }
        }

        float rm0 = -1e30f, rm1 = -1e30f;
#pragma unroll
        for (int nb = 0; nb < 16; nb++) {
            rm0 = fmaxf(rm0, fmaxf(acc_s[nb][0], acc_s[nb][1]));
            rm1 = fmaxf(rm1, fmaxf(acc_s[nb][2], acc_s[nb][3]));
        }
        rm0 = fmaxf(rm0, __shfl_xor_sync(0xffffffffu, rm0, 1));
        rm0 = fmaxf(rm0, __shfl_xor_sync(0xffffffffu, rm0, 2));
        rm1 = fmaxf(rm1, __shfl_xor_sync(0xffffffffu, rm1, 1));
        rm1 = fmaxf(rm1, __shfl_xor_sync(0xffffffffu, rm1, 2));

        float mn0 = fmaxf(m0, rm0), mn1 = fmaxf(m1, rm1);
        float sc0 = __expf(m0 - mn0), sc1 = __expf(m1 - mn1);
        m0 = mn0; m1 = mn1;

        uint32_t pk[16], qk[16];
        float ls0 = 0.0f, ls1 = 0.0f;
#pragma unroll
        for (int nb = 0; nb < 16; nb++) {
            float e0 = __expf(acc_s[nb][0] - mn0);
            float e1 = __expf(acc_s[nb][1] - mn0);
            float e2 = __expf(acc_s[nb][2] - mn1);
            float e3 = __expf(acc_s[nb][3] - mn1);
            ls0 += e0 + e1; ls1 += e2 + e3;
            __nv_bfloat162 h0 = __float22bfloat162_rn(make_float2(e0, e1));
            __nv_bfloat162 h1 = __float22bfloat162_rn(make_float2(e2, e3));
            pk[nb] = *reinterpret_cast<uint32_t*>(&h0);
            qk[nb] = *reinterpret_cast<uint32_t*>(&h1);
        }
        ls0 += __shfl_xor_sync(0xffffffffu, ls0, 1);
        ls0 += __shfl_xor_sync(0xffffffffu, ls0, 2);
        ls1 += __shfl_xor_sync(0xffffffffu, ls1, 1);
        ls1 += __shfl_xor_sync(0xffffffffu, ls1, 2);
        l0 = l0 * sc0 + ls0;
        l1 = l1 * sc1 + ls1;

#pragma unroll
        for (int nb = 0; nb < 32; nb++) {
            acc_o[nb][0] *= sc0; acc_o[nb][1] *= sc0;
            acc_o[nb][2] *= sc1; acc_o[nb][3] *= sc1;
        }

#pragma unroll
        for (int j = 0; j < 8; j++) {
            uint32_t a0 = pk[2 * j], a1 = qk[2 * j], a2 = pk[2 * j + 1], a3 = qk[2 * j + 1];
#pragma unroll
            for (int on = 0; on < 16; on++) {
                uint32_t d0, d1, d2, d3;
                int grp = lane >> 3;
                int rv = 16 * j + ((grp & 1) << 3) + (lane & 7);
                int colbyte = on * 32 + ((grp >> 1) << 4);
                LDSM_X4T(d0, d1, d2, d3, tile_addr(ms[b], rv, colbyte));
                MMA16816(acc_o[on * 2],     a0, a1, a2, a3, d0, d1);
                MMA16816(acc_o[on * 2 + 1], a0, a1, a2, a3, d2, d3);
            }
        }
        __syncthreads();
    }

    float inv0 = 1.0f / l0, inv1 = 1.0f / l1;
    long r0 = row0 + 16 * wid + (lane >> 2);
    long r1 = r0 + 8;
#pragma unroll
    for (int nb = 0; nb < 32; nb++) {
        int cn = 256 + nb * 8 + (lane & 3) * 2;
        float v0 = acc_o[nb][0] * inv0, v1 = acc_o[nb][1] * inv0;
        float v2 = acc_o[nb][2] * inv1, v3 = acc_o[nb][3] * inv1;
        *(float2*)(cat + r0 * 512 + cn) = make_float2(v0, v1);
        *(float2*)(cat + r1 * 512 + cn) = make_float2(v2, v3);
        __nv_bfloat162 h0 = __float22bfloat162_rn(make_float2(v0, v1));
        __nv_bfloat162 h1 = __float22bfloat162_rn(make_float2(v2, v3));
        *(uint32_t*)(catb + r0 * 512 + cn) = *reinterpret_cast<uint32_t*>(&h0);
        *(uint32_t*)(catb + r1 * 512 + cn) = *reinterpret_cast<uint32_t*>(&h1);
    }
}

// ---------------------------------------------------------------------------
// G3: h = silu(catb @ w1T^T + b1) -> bf16. BM=128 BN=128 BK=64, 256 thr.
// ---------------------------------------------------------------------------
__global__ void __launch_bounds__(256, 2)
gemm_g3(const __nv_bfloat16* __restrict__ A, const __nv_bfloat16* __restrict__ B,
        const float* __restrict__ bias, __nv_bfloat16* __restrict__ Cb,
        int K, int ldcb)
{
    extern __shared__ char dsm[];
    const uint32_t sbase = (smem_u32(dsm) + 1023) & ~1023u;
    const int tid = threadIdx.x;
    const int wid = tid >> 5, lane = tid & 31;
    const int wm = wid & 3;
    const int wn = wid >> 2;
    const long row0 = (long)blockIdx.y * 128;
    const long col0 = (long)blockIdx.x * 128;

    const uint32_t sA[2] = { sbase,         sbase + 32768 };
    const uint32_t sB[2] = { sbase + 16384, sbase + 49152 };

    float acc[2][8][4];
#pragma unroll
    for (int i = 0; i < 2; i++)
#pragma unroll
        for (int j = 0; j < 8; j++)
#pragma unroll
            for (int q = 0; q < 4; q++) acc[i][j][q] = 0.0f;

    const char* Ag = (const char*)(A + row0 * K);
    const char* Bg = (const char*)(B + col0 * K);
    const long rowb = (long)K * 2;
    const int lr = tid >> 3;
    const int lc = tid & 7;
    const int nchunks = K >> 6;

    {
#pragma unroll
        for (int j = 0; j < 4; j++) {
            int r = lr + j * 32;
            uint32_t off = (uint32_t)(r * 128) + (uint32_t)((lc ^ (r & 7)) << 4);
            CP_ASYNC16(sA[0] + off, Ag + (long)r * rowb + lc * 16);
            CP_ASYNC16(sB[0] + off, Bg + (long)r * rowb + lc * 16);
        }
        CP_COMMIT();
    }

    for (int i = 0; i < nchunks; i++) {
        const int b = i & 1;
        if (i + 1 < nchunks) {
            const long kb = (long)(i + 1) << 7;
#pragma unroll
            for (int j = 0; j < 4; j++) {
                int r = lr + j * 32;
                uint32_t off = (uint32_t)(r * 128) + (uint32_t)((lc ^ (r & 7)) << 4);
                CP_ASYNC16(sA[1 - b] + off, Ag + (long)r * rowb + kb + lc * 16);
                CP_ASYNC16(sB[1 - b] + off, Bg + (long)r * rowb + kb + lc * 16);
            }
            CP_COMMIT();
            CP_WAIT(1);
        } else {
            CP_WAIT(0);
        }
        __syncthreads();

#pragma unroll
        for (int ks = 0; ks < 4; ks++) {
            uint32_t af[2][4];
#pragma unroll
            for (int mi = 0; mi < 2; mi++) {
                int r = wm * 32 + mi * 16 + (lane & 15);
                int cch = ks * 2 + (lane >> 4);
                uint32_t addr = sA[b] + (uint32_t)(r * 128) + (uint32_t)((cch ^ (r & 7)) << 4);
                LDSM_X4(af[mi][0], af[mi][1], af[mi][2], af[mi][3], addr);
            }
            uint32_t bf[4][4];
#pragma unroll
            for (int nt = 0; nt < 4; nt++) {
                int r = wn * 64 + nt * 16 + (lane & 7) + ((lane >> 4) << 3);
                int cch = ks * 2 + ((lane >> 3) & 1);
                uint32_t addr = sB[b] + (uint32_t)(r * 128) + (uint32_t)((cch ^ (r & 7)) << 4);
                LDSM_X4(bf[nt][0], bf[nt][1], bf[nt][2], bf[nt][3], addr);
            }
#pragma unroll
            for (int mi = 0; mi < 2; mi++)
#pragma unroll
                for (int ni = 0; ni < 8; ni++) {
                    uint32_t b0 = bf[ni >> 1][(ni & 1) * 2];
                    uint32_t b1 = bf[ni >> 1][(ni & 1) * 2 + 1];
                    MMA16816(acc[mi][ni], af[mi][0], af[mi][1], af[mi][2], af[mi][3], b0, b1);
                }
        }
        __syncthreads();
    }

#pragma unroll
    for (int mi = 0; mi < 2; mi++) {
#pragma unroll
        for (int h = 0; h < 2; h++) {
            long r = row0 + wm * 32 + mi * 16 + (lane >> 2) + h * 8;
#pragma unroll
            for (int ni = 0; ni < 8; ni++) {
                int cn = (int)col0 + wn * 64 + ni * 8 + (lane & 3) * 2;
                float v0 = acc[mi][ni][h * 2]     + bias[cn];
                float v1 = acc[mi][ni][h * 2 + 1] + bias[cn + 1];
                v0 = v0 / (1.0f + __expf(-v0));
                v1 = v1 / (1.0f + __expf(-v1));
                __nv_bfloat162 h2 = __float22bfloat162_rn(make_float2(v0, v1));
                *(uint32_t*)(Cb + r * ldcb + cn) = *reinterpret_cast<uint32_t*>(&h2);
            }
        }
    }
}

// ---------------------------------------------------------------------------
// G4: g = sigmoid(hb @ w2T^T + b2), CTA tile = 128 rows (64 b x 2 m) x 128 c.
// In-CTA reduction over b -> newmem direct (no gate buffer, no atomics).
// grid (2, 512): blockIdx.x = c-half, blockIdx.y = m-pair.
// ---------------------------------------------------------------------------
__global__ void __launch_bounds__(256, 2)
gemm_g4(const __nv_bfloat16* __restrict__ A, const __nv_bfloat16* __restrict__ B,
        const float* __restrict__ bias,
        const float* __restrict__ mem, const float* __restrict__ xm,
        float* __restrict__ nm)
{
    extern __shared__ char dsm[];
    const uint32_t sbase = (smem_u32(dsm) + 1023) & ~1023u;
    const int tid = threadIdx.x;
    const int wid = tid >> 5, lane = tid & 31;
    const int wm = wid & 3;
    const int wn = wid >> 2;
    const int m0 = blockIdx.y * 2;
    const int col0 = blockIdx.x * 128;
    const int K = 1024;

    const uint32_t sA[2] = { sbase,         sbase + 32768 };
    const uint32_t sB[2] = { sbase + 16384, sbase + 49152 };

    float acc[2][8][4];
#pragma unroll
    for (int i = 0; i < 2; i++)
#pragma unroll
        for (int j = 0; j < 8; j++)
#pragma unroll
            for (int q = 0; q < 4; q++) acc[i][j][q] = 0.0f;

    const char* Ag = (const char*)A;
    const char* Bg = (const char*)(B + (long)col0 * K);
    const long rowb = (long)K * 2;   // 2048 bytes
    const int lr = tid >> 3;
    const int lc = tid & 7;
    const int nchunks = K >> 6;      // 16

    // strided row map: local i -> global row (i&63)*1024 + m0 + (i>>6)
#pragma unroll
    for (int j = 0; j < 4; j++) {
        int i = lr + j * 32;
        long gr = ((long)(i & 63) << 10) + m0 + (i >> 6);
        uint32_t off = (uint32_t)(i * 128) + (uint32_t)((lc ^ (i & 7)) << 4);
        CP_ASYNC16(sA[0] + off, Ag + gr * rowb + lc * 16);
        CP_ASYNC16(sB[0] + off, Bg + (long)i * rowb + lc * 16);
    }
    CP_COMMIT();

    for (int it = 0; it < nchunks; it++) {
        const int b = it & 1;
        if (it + 1 < nchunks) {
            const long kb = (long)(it + 1) << 7;
#pragma unroll
            for (int j = 0; j < 4; j++) {
                int i = lr + j * 32;
                long gr = ((long)(i & 63) << 10) + m0 + (i >> 6);
                uint32_t off = (uint32_t)(i * 128) + (uint32_t)((lc ^ (i & 7)) << 4);
                CP_ASYNC16(sA[1 - b] + off, Ag + gr * rowb + kb + lc * 16);
                CP_ASYNC16(sB[1 - b] + off, Bg + (long)i * rowb + kb + lc * 16);
            }
            CP_COMMIT();
            CP_WAIT(1);
        } else {
            CP_WAIT(0);
        }
        __syncthreads();

#pragma unroll
        for (int ks = 0; ks < 4; ks++) {
            uint32_t af[2][4];
#pragma unroll
            for (int mi = 0; mi < 2; mi++) {
                int r = wm * 32 + mi * 16 + (lane & 15);
                int cch = ks * 2 + (lane >> 4);
                uint32_t addr = sA[b] + (uint32_t)(r * 128) + (uint32_t)((cch ^ (r & 7)) << 4);
                LDSM_X4(af[mi][0], af[mi][1], af[mi][2], af[mi][3], addr);
            }
            uint32_t bf[4][4];
#pragma unroll
            for (int nt = 0; nt < 4; nt++) {
                int r = wn * 64 + nt * 16 + (lane & 7) + ((lane >> 4) << 3);
                int cch = ks * 2 + ((lane >> 3) & 1);
                uint32_t addr = sB[b] + (uint32_t)(r * 128) + (uint32_t)((cch ^ (r & 7)) << 4);
                LDSM_X4(bf[nt][0], bf[nt][1], bf[nt][2], bf[nt][3], addr);
            }
#pragma unroll
            for (int mi = 0; mi < 2; mi++)
#pragma unroll
                for (int ni = 0; ni < 8; ni++) {
                    uint32_t b0 = bf[ni >> 1][(ni & 1) * 2];
                    uint32_t b1 = bf[ni >> 1][(ni & 1) * 2 + 1];
                    MMA16816(acc[mi][ni], af[mi][0], af[mi][1], af[mi][2], af[mi][3], b0, b1);
                }
        }
        __syncthreads();
    }

    // ---- epilogue: blend into padded smem (528B row stride), reduce b ----
    // (tile smem is dead after final __syncthreads; reuse from sbase)
#pragma unroll
    for (int mi = 0; mi < 2; mi++) {
#pragma unroll
        for (int h = 0; h < 2; h++) {
            int il = wm * 32 + mi * 16 + (lane >> 2) + h * 8;   // local row
            int bb = il & 63;
            int mloc = il >> 6;
#pragma unroll
            for (int ni = 0; ni < 8; ni++) {
                int cl = wn * 64 + ni * 8 + (lane & 3) * 2;     // local col
                int cn = col0 + cl;
                float v0 = acc[mi][ni][h * 2]     + bias[cn];
                float v1 = acc[mi][ni][h * 2 + 1] + bias[cn + 1];
                float g0 = 1.0f / (1.0f + __expf(-v0));
                float g1 = 1.0f / (1.0f + __expf(-v1));
                float mm0 = mem[(m0 + mloc) * 256 + cn];
                float mm1 = mem[(m0 + mloc) * 256 + cn + 1];
                float xv0 = xm[bb * 256 + cn];
                float xv1 = xm[bb * 256 + cn + 1];
                float o0 = fmaf(xv0 - mm0, g0, mm0) * (1.0f / 64.0f);
                float o1 = fmaf(xv1 - mm1, g1, mm1) * (1.0f / 64.0f);
                *(float2*)(dsm + (sbase - smem_u32(dsm)) + il * 528 + cl * 4) = make_float2(o0, o1);
            }
        }
    }
    __syncthreads();

    // reduce: thread t -> (mloc = t>>7, c = t&127), sum 64 b-rows
    {
        int mloc = tid >> 7;
        int c = tid & 127;
        const char* sred = dsm + (sbase - smem_u32(dsm));
        float s = 0.0f;
#pragma unroll
        for (int k = 0; k < 64; k++) {
            int il = mloc * 64 + k;
            s += *(const float*)(sred + il * 528 + c * 4);
        }
        nm[(m0 + mloc) * 256 + col0 + c] = s;
    }
}

// ---------------------------------------------------------------------------
// convert_x (R4 version, no atomics)
// ---------------------------------------------------------------------------
__global__ void convert_x(const float4* __restrict__ x4, float4* __restrict__ cat4,
                          uint2* __restrict__ xb2, uint2* __restrict__ catb2)
{
    long i = (long)blockIdx.x * 256 + threadIdx.x;
    long row = i >> 6;
    long c4 = i & 63;
    float4 v = x4[i];
    cat4[row * 128 + c4] = v;
    __nv_bfloat162 l = __float22bfloat162_rn(make_float2(v.x, v.y));
    __nv_bfloat162 h = __float22bfloat162_rn(make_float2(v.z, v.w));
    uint2 pk = make_uint2(*reinterpret_cast<uint32_t*>(&l), *reinterpret_cast<uint32_t*>(&h));
    xb2[i] = pk;
    catb2[row * 128 + c4] = pk;
}

// merged weight conversions (memb + w1T + w2T), grid 2048 x 256
__global__ void conv_all(const float* __restrict__ mem, const float* __restrict__ w1,
                         const float* __restrict__ w2,
                         __nv_bfloat16* __restrict__ memb, __nv_bfloat16* __restrict__ w1T,
                         __nv_bfloat16* __restrict__ w2T)
{
    int i = blockIdx.x * 256 + threadIdx.x;   // 0..524287
    {   // w1 [512,1024] -> w1T [1024,512]
        int k = i >> 10, n = i & 1023;
        w1T[n * 512 + k] = __float2bfloat16(w1[i]);
    }
    if (i < 262144) {
        memb[i] = __float2bfloat16(mem[i]);
        int f = i >> 8, c = i & 255;          // w2 [1024,256] -> w2T [256,1024]
        w2T[c * 1024 + f] = __float2bfloat16(w2[i]);
    }
}

// ---------------------------------------------------------------------------
// xmean: 2-stage, no atomics. stage1 grid 512 (= 64 b x 8 chunks of 128 t).
// ---------------------------------------------------------------------------
__global__ void xmean_part(const float* __restrict__ x, float* __restrict__ xpart)
{
    int b = blockIdx.x >> 3, ch = blockIdx.x & 7;
    int c = threadIdx.x;
    const float* p = x + ((long)b * 1024 + ch * 128) * 256 + c;
    float s = 0.0f;
#pragma unroll 8
    for (int t = 0; t < 128; t++) s += p[t * 256];
    xpart[blockIdx.x * 256 + c] = s * (1.0f / 1024.0f);
}

__global__ void xmean_comb(const float* __restrict__ xpart, float* __restrict__ xmn)
{
    int i = blockIdx.x * 256 + threadIdx.x;   // 0..16383
    int b = i >> 8, c = i & 255;
    float s = 0.0f;
#pragma unroll
    for (int k = 0; k < 8; k++) s += xpart[(b * 8 + k) * 256 + c];
    xmn[i] = s;
}

// ---------------------------------------------------------------------------
extern "C" void kernel_launch(void* const* d_in, const int* in_sizes, int n_in,
                              void* d_out, int out_size)
{
    const float* x      = (const float*)d_in[0];
    const float* memory = (const float*)d_in[1];
    const float* w1     = (const float*)d_in[2];
    const float* b1     = (const float*)d_in[3];
    const float* w2     = (const float*)d_in[4];
    const float* b2     = (const float*)d_in[5];

    float* out    = (float*)d_out;
    float* cat    = out;               // [65536,512]
    float* newmem = out + 33554432ll;  // [1024,256]

    __nv_bfloat16 *xb, *catb, *hb, *memb, *w1T, *w2T;
    float *xp, *xmn;
    cudaGetSymbolAddress((void**)&xb, g_xb);
    cudaGetSymbolAddress((void**)&catb, g_catb);
    cudaGetSymbolAddress((void**)&hb, g_hb);
    cudaGetSymbolAddress((void**)&memb, g_memb);
    cudaGetSymbolAddress((void**)&w1T, g_w1T);
    cudaGetSymbolAddress((void**)&w2T, g_w2T);
    cudaGetSymbolAddress((void**)&xp, g_xpart);
    cudaGetSymbolAddress((void**)&xmn, g_xmean);

    const int SMEM_G3 = 1024 + 65536;           // guard + 2x(16KB+16KB)
    const int SMEM_G4 = 1024 + 128 * 528;       // guard + max(tiles, reduce buf)
    const int SMEM_F  = 1024 + 3 * 65536;       // guard + x + 2 mem bufs
    cudaFuncSetAttribute(gemm_g3, cudaFuncAttributeMaxDynamicSharedMemorySize, SMEM_G3);
    cudaFuncSetAttribute(gemm_g4, cudaFuncAttributeMaxDynamicSharedMemorySize, SMEM_G4);
    cudaFuncSetAttribute(flash_attn, cudaFuncAttributeMaxDynamicSharedMemorySize, SMEM_F);

    // conversions + xmean
    conv_all<<<2048, 256>>>(memory, w1, w2, memb, w1T, w2T);
    convert_x<<<16384, 256>>>((const float4*)x, (float4*)cat, (uint2*)xb, (uint2*)catb);
    xmean_part<<<512, 256>>>(x, xp);
    xmean_comb<<<64, 256>>>(xp, xmn);

    // fused G1 + softmax + G2 -> cat[:,256:512] fp32 + catb[:,256:512] bf16
    flash_attn<<<512, 256, SMEM_F>>>(xb, memb, cat, catb);

    // G3: h = silu(catb @ w1T^T + b1) -> hb bf16 [65536,1024]
    gemm_g3<<<dim3(8, 512), 256, SMEM_G3>>>(catb, w1T, b1, hb, 512, 1024);

    // G4: g = sigmoid(hb @ w2T^T + b2) -> newmem (in-CTA b-reduction)
    gemm_g4<<<dim3(2, 512), 256, SMEM_G4>>>(hb, w2T, b2, memory, xmn, newmem);
}

// round 12
// speedup vs baseline: 1.1497x; 1.0460x over previous
#include <cuda_runtime.h>
#include <cuda_bf16.h>
#include <cstdint>
#include <math.h>

// ===========================================================================
// DynamicMemoryBank — R11 (= R9 design; third attempt after 2x container fail)
//   flash: prologue reads x fp32 -> cat0/catb0/xs-smem + xmean partials;
//          mainloop: retrieved = softmax(x@mem^T)@mem -> cat1 fp32 + catb1
//   xmean_comb: combine partials (scale 1/1024)
//   G3: h = silu(catb @ w1T^T + b1) -> bf16
//   G4: g = sigmoid(hb @ w2T^T + b2), CTA rows = 64 b x 2 m,
//       in-CTA reduce over b -> newmem direct store
// ===========================================================================

__device__ __forceinline__ uint32_t smem_u32(const void* p) {
    uint32_t a;
    asm("{ .reg .u64 t; cvta.to.shared.u64 t, %1; cvt.u32.u64 %0, t; }" : "=r"(a) : "l"(p));
    return a;
}

#define LDSM_X4(R0, R1, R2, R3, ADDR) \
    asm volatile("ldmatrix.sync.aligned.m8n8.x4.shared.b16 {%0,%1,%2,%3}, [%4];" \
        : "=r"(R0), "=r"(R1), "=r"(R2), "=r"(R3) : "r"(ADDR))

#define LDSM_X4T(R0, R1, R2, R3, ADDR) \
    asm volatile("ldmatrix.sync.aligned.m8n8.x4.trans.shared.b16 {%0,%1,%2,%3}, [%4];" \
        : "=r"(R0), "=r"(R1), "=r"(R2), "=r"(R3) : "r"(ADDR))

#define MMA16816(C, A0, A1, A2, A3, B0, B1) \
    asm volatile("mma.sync.aligned.m16n8k16.row.col.f32.bf16.bf16.f32 " \
        "{%0,%1,%2,%3}, {%4,%5,%6,%7}, {%8,%9}, {%0,%1,%2,%3};" \
        : "+f"((C)[0]), "+f"((C)[1]), "+f"((C)[2]), "+f"((C)[3]) \
        : "r"(A0), "r"(A1), "r"(A2), "r"(A3), "r"(B0), "r"(B1))

#define CP_ASYNC16(DST, SRC) \
    asm volatile("cp.async.cg.shared.global [%0], [%1], 16;" :: "r"(DST), "l"(SRC))
#define CP_COMMIT() asm volatile("cp.async.commit_group;" ::: "memory")
#define CP_WAIT(N)  asm volatile("cp.async.wait_group %0;" :: "n"(N) : "memory")

// ---------------------------------------------------------------------------
// scratch
// ---------------------------------------------------------------------------
__device__ __nv_bfloat16 g_catb[33554432];    // [65536,512]
__device__ __nv_bfloat16 g_hb[67108864];      // [65536,1024]
__device__ __nv_bfloat16 g_memb[262144];      // [1024,256]
__device__ __nv_bfloat16 g_w1T[524288];       // [1024,512]
__device__ __nv_bfloat16 g_w2T[262144];       // [256,1024]
__device__ float         g_xpart[131072];     // [512,256] xmean partials (raw sums)
__device__ float         g_xmean[16384];      // [64,256]

// swizzled addr within a 128-row x 512B tile (16B-chunk granularity)
__device__ __forceinline__ uint32_t tile_addr(uint32_t base, int r, int colbyte) {
    return base + (uint32_t)(r * 512) + (uint32_t)(colbyte & ~127)
         + (uint32_t)(((((colbyte >> 4) & 7) ^ (r & 7)) << 4));
}

// ---------------------------------------------------------------------------
// Flash kernel: per CTA 128 rows of x; 8 chunks of 128 mem rows.
// Prologue converts x fp32 -> cat0/catb0/xs-tile and produces xmean partials.
// ---------------------------------------------------------------------------
__global__ void __launch_bounds__(256, 1)
flash_attn(const float* __restrict__ x, const __nv_bfloat16* __restrict__ memb,
           float* __restrict__ cat, __nv_bfloat16* __restrict__ catb,
           float* __restrict__ xpart)
{
    extern __shared__ char dsm[];
    const uint32_t dbase = smem_u32(dsm);
    const uint32_t sbase = (dbase + 1023) & ~1023u;
    const uint32_t xs = sbase;
    const uint32_t ms[2] = { sbase + 65536, sbase + 131072 };
    char* const sptr = dsm + (sbase - dbase);

    const int tid = threadIdx.x;
    const int wid = tid >> 5, lane = tid & 31;
    const long row0 = (long)blockIdx.x * 128;

    // kick off mem chunk 0 first so it flows under the prologue
    {
        const char* Mg = (const char*)memb;
#pragma unroll
        for (int j = 0; j < 16; j++) {
            int idx = tid + j * 256;
            int r = idx >> 5;
            int colbyte = (idx & 31) << 4;
            CP_ASYNC16(tile_addr(ms[0], r, colbyte), Mg + (long)r * 512 + colbyte);
        }
        CP_COMMIT();
    }

    // ---- prologue: x fp32 -> cat0 fp32, catb0 bf16, xs smem tile, col sums --
    {
        const float4* Xg = (const float4*)x + row0 * 64;   // 64 f4 per row
        float4* cat4  = (float4*)cat;
        uint2*  catb2 = (uint2*)catb;
        float4 csum = make_float4(0.f, 0.f, 0.f, 0.f);
#pragma unroll 8
        for (int it = 0; it < 32; it++) {
            int idx = it * 256 + tid;          // 0..8191
            int r = idx >> 6;                  // 0..127
            int c4 = idx & 63;
            float4 v = Xg[idx];
            cat4[(row0 + r) * 128 + c4] = v;
            __nv_bfloat162 lo = __float22bfloat162_rn(make_float2(v.x, v.y));
            __nv_bfloat162 hi = __float22bfloat162_rn(make_float2(v.z, v.w));
            uint2 pk = make_uint2(*reinterpret_cast<uint32_t*>(&lo),
                                  *reinterpret_cast<uint32_t*>(&hi));
            catb2[(row0 + r) * 128 + c4] = pk;
            int colbyte = c4 * 8;
            uint32_t addr = tile_addr(xs, r, colbyte & ~15) + (colbyte & 8);
            *(uint2*)(dsm + (addr - dbase)) = pk;
            csum.x += v.x; csum.y += v.y; csum.z += v.z; csum.w += v.w;
        }
        // reduce col sums over the 4 thread groups (tid>>6), cols (tid&63)*4
        float4* red = (float4*)(sptr + 196608);
        red[tid] = csum;
        __syncthreads();
        if (tid < 64) {
            float4 a = red[tid], b = red[tid + 64], c = red[tid + 128], d = red[tid + 192];
            float4 s = make_float4(a.x + b.x + c.x + d.x, a.y + b.y + c.y + d.y,
                                   a.z + b.z + c.z + d.z, a.w + b.w + c.w + d.w);
            ((float4*)xpart)[blockIdx.x * 64 + tid] = s;
        }
    }

    float acc_o[32][4];
#pragma unroll
    for (int b = 0; b < 32; b++)
#pragma unroll
        for (int q = 0; q < 4; q++) acc_o[b][q] = 0.0f;
    float m0 = -1e30f, m1 = -1e30f, l0 = 0.0f, l1 = 0.0f;

    for (int c = 0; c < 8; c++) {
        const int b = c & 1;
        if (c + 1 < 8) {
            const char* Mg = (const char*)(memb + (long)(c + 1) * 128 * 256);
#pragma unroll
            for (int j = 0; j < 16; j++) {
                int idx = tid + j * 256;
                int r = idx >> 5;
                int colbyte = (idx & 31) << 4;
                CP_ASYNC16(tile_addr(ms[1 - b], r, colbyte), Mg + (long)r * 512 + colbyte);
            }
            CP_COMMIT();
            CP_WAIT(1);
        } else {
            CP_WAIT(0);
        }
        __syncthreads();

        float acc_s[16][4];
#pragma unroll
        for (int nb = 0; nb < 16; nb++)
#pragma unroll
            for (int q = 0; q < 4; q++) acc_s[nb][q] = 0.0f;

#pragma unroll
        for (int ks = 0; ks < 16; ks++) {
            uint32_t a0, a1, a2, a3;
            {
                int r = 16 * wid + (lane & 15);
                int colbyte = ks * 32 + ((lane >> 4) << 4);
                LDSM_X4(a0, a1, a2, a3, tile_addr(xs, r, colbyte));
            }
#pragma unroll
            for (int nb2 = 0; nb2 < 8; nb2++) {
                uint32_t d0, d1, d2, d3;
                int rn = nb2 * 16 + (lane & 7) + ((lane >> 4) << 3);
                int colbyte = ks * 32 + (((lane >> 3) & 1) << 4);
                LDSM_X4(d0, d1, d2, d3, tile_addr(ms[b], rn, colbyte));
                MMA16816(acc_s[nb2 * 2],     a0, a1, a2, a3, d0, d1);
                MMA16816(acc_s[nb2 * 2 + 1], a0, a1, a2, a3, d2, d3);
            }
        }

        float rm0 = -1e30f, rm1 = -1e30f;
#pragma unroll
        for (int nb = 0; nb < 16; nb++) {
            rm0 = fmaxf(rm0, fmaxf(acc_s[nb][0], acc_s[nb][1]));
            rm1 = fmaxf(rm1, fmaxf(acc_s[nb][2], acc_s[nb][3]));
        }
        rm0 = fmaxf(rm0, __shfl_xor_sync(0xffffffffu, rm0, 1));
        rm0 = fmaxf(rm0, __shfl_xor_sync(0xffffffffu, rm0, 2));
        rm1 = fmaxf(rm1, __shfl_xor_sync(0xffffffffu, rm1, 1));
        rm1 = fmaxf(rm1, __shfl_xor_sync(0xffffffffu, rm1, 2));

        float mn0 = fmaxf(m0, rm0), mn1 = fmaxf(m1, rm1);
        float sc0 = __expf(m0 - mn0), sc1 = __expf(m1 - mn1);
        m0 = mn0; m1 = mn1;

        uint32_t pk[16], qk[16];
        float ls0 = 0.0f, ls1 = 0.0f;
#pragma unroll
        for (int nb = 0; nb < 16; nb++) {
            float e0 = __expf(acc_s[nb][0] - mn0);
            float e1 = __expf(acc_s[nb][1] - mn0);
            float e2 = __expf(acc_s[nb][2] - mn1);
            float e3 = __expf(acc_s[nb][3] - mn1);
            ls0 += e0 + e1; ls1 += e2 + e3;
            __nv_bfloat162 h0 = __float22bfloat162_rn(make_float2(e0, e1));
            __nv_bfloat162 h1 = __float22bfloat162_rn(make_float2(e2, e3));
            pk[nb] = *reinterpret_cast<uint32_t*>(&h0);
            qk[nb] = *reinterpret_cast<uint32_t*>(&h1);
        }
        ls0 += __shfl_xor_sync(0xffffffffu, ls0, 1);
        ls0 += __shfl_xor_sync(0xffffffffu, ls0, 2);
        ls1 += __shfl_xor_sync(0xffffffffu, ls1, 1);
        ls1 += __shfl_xor_sync(0xffffffffu, ls1, 2);
        l0 = l0 * sc0 + ls0;
        l1 = l1 * sc1 + ls1;

#pragma unroll
        for (int nb = 0; nb < 32; nb++) {
            acc_o[nb][0] *= sc0; acc_o[nb][1] *= sc0;
            acc_o[nb][2] *= sc1; acc_o[nb][3] *= sc1;
        }

#pragma unroll
        for (int j = 0; j < 8; j++) {
            uint32_t a0 = pk[2 * j], a1 = qk[2 * j], a2 = pk[2 * j + 1], a3 = qk[2 * j + 1];
#pragma unroll
            for (int on = 0; on < 16; on++) {
                uint32_t d0, d1, d2, d3;
                int grp = lane >> 3;
                int rv = 16 * j + ((grp & 1) << 3) + (lane & 7);
                int colbyte = on * 32 + ((grp >> 1) << 4);
                LDSM_X4T(d0, d1, d2, d3, tile_addr(ms[b], rv, colbyte));
                MMA16816(acc_o[on * 2],     a0, a1, a2, a3, d0, d1);
                MMA16816(acc_o[on * 2 + 1], a0, a1, a2, a3, d2, d3);
            }
        }
        __syncthreads();
    }

    float inv0 = 1.0f / l0, inv1 = 1.0f / l1;
    long r0 = row0 + 16 * wid + (lane >> 2);
    long r1 = r0 + 8;
#pragma unroll
    for (int nb = 0; nb < 32; nb++) {
        int cn = 256 + nb * 8 + (lane & 3) * 2;
        float v0 = acc_o[nb][0] * inv0, v1 = acc_o[nb][1] * inv0;
        float v2 = acc_o[nb][2] * inv1, v3 = acc_o[nb][3] * inv1;
        *(float2*)(cat + r0 * 512 + cn) = make_float2(v0, v1);
        *(float2*)(cat + r1 * 512 + cn) = make_float2(v2, v3);
        __nv_bfloat162 h0 = __float22bfloat162_rn(make_float2(v0, v1));
        __nv_bfloat162 h1 = __float22bfloat162_rn(make_float2(v2, v3));
        *(uint32_t*)(catb + r0 * 512 + cn) = *reinterpret_cast<uint32_t*>(&h0);
        *(uint32_t*)(catb + r1 * 512 + cn) = *reinterpret_cast<uint32_t*>(&h1);
    }
}

// ---------------------------------------------------------------------------
// G3: h = silu(catb @ w1T^T + b1) -> bf16. BM=128 BN=128 BK=64, 256 thr.
// ---------------------------------------------------------------------------
__global__ void __launch_bounds__(256, 2)
gemm_g3(const __nv_bfloat16* __restrict__ A, const __nv_bfloat16* __restrict__ B,
        const float* __restrict__ bias, __nv_bfloat16* __restrict__ Cb,
        int K, int ldcb)
{
    extern __shared__ char dsm[];
    const uint32_t sbase = (smem_u32(dsm) + 1023) & ~1023u;
    const int tid = threadIdx.x;
    const int wid = tid >> 5, lane = tid & 31;
    const int wm = wid & 3;
    const int wn = wid >> 2;
    const long row0 = (long)blockIdx.y * 128;
    const long col0 = (long)blockIdx.x * 128;

    const uint32_t sA[2] = { sbase,         sbase + 32768 };
    const uint32_t sB[2] = { sbase + 16384, sbase + 49152 };

    float acc[2][8][4];
#pragma unroll
    for (int i = 0; i < 2; i++)
#pragma unroll
        for (int j = 0; j < 8; j++)
#pragma unroll
            for (int q = 0; q < 4; q++) acc[i][j][q] = 0.0f;

    const char* Ag = (const char*)(A + row0 * K);
    const char* Bg = (const char*)(B + col0 * K);
    const long rowb = (long)K * 2;
    const int lr = tid >> 3;
    const int lc = tid & 7;
    const int nchunks = K >> 6;

    {
#pragma unroll
        for (int j = 0; j < 4; j++) {
            int r = lr + j * 32;
            uint32_t off = (uint32_t)(r * 128) + (uint32_t)((lc ^ (r & 7)) << 4);
            CP_ASYNC16(sA[0] + off, Ag + (long)r * rowb + lc * 16);
            CP_ASYNC16(sB[0] + off, Bg + (long)r * rowb + lc * 16);
        }
        CP_COMMIT();
    }

    for (int i = 0; i < nchunks; i++) {
        const int b = i & 1;
        if (i + 1 < nchunks) {
            const long kb = (long)(i + 1) << 7;
#pragma unroll
            for (int j = 0; j < 4; j++) {
                int r = lr + j * 32;
                uint32_t off = (uint32_t)(r * 128) + (uint32_t)((lc ^ (r & 7)) << 4);
                CP_ASYNC16(sA[1 - b] + off, Ag + (long)r * rowb + kb + lc * 16);
                CP_ASYNC16(sB[1 - b] + off, Bg + (long)r * rowb + kb + lc * 16);
            }
            CP_COMMIT();
            CP_WAIT(1);
        } else {
            CP_WAIT(0);
        }
        __syncthreads();

#pragma unroll
        for (int ks = 0; ks < 4; ks++) {
            uint32_t af[2][4];
#pragma unroll
            for (int mi = 0; mi < 2; mi++) {
                int r = wm * 32 + mi * 16 + (lane & 15);
                int cch = ks * 2 + (lane >> 4);
                uint32_t addr = sA[b] + (uint32_t)(r * 128) + (uint32_t)((cch ^ (r & 7)) << 4);
                LDSM_X4(af[mi][0], af[mi][1], af[mi][2], af[mi][3], addr);
            }
            uint32_t bf[4][4];
#pragma unroll
            for (int nt = 0; nt < 4; nt++) {
                int r = wn * 64 + nt * 16 + (lane & 7) + ((lane >> 4) << 3);
                int cch = ks * 2 + ((lane >> 3) & 1);
                uint32_t addr = sB[b] + (uint32_t)(r * 128) + (uint32_t)((cch ^ (r & 7)) << 4);
                LDSM_X4(bf[nt][0], bf[nt][1], bf[nt][2], bf[nt][3], addr);
            }
#pragma unroll
            for (int mi = 0; mi < 2; mi++)
#pragma unroll
                for (int ni = 0; ni < 8; ni++) {
                    uint32_t b0 = bf[ni >> 1][(ni & 1) * 2];
                    uint32_t b1 = bf[ni >> 1][(ni & 1) * 2 + 1];
                    MMA16816(acc[mi][ni], af[mi][0], af[mi][1], af[mi][2], af[mi][3], b0, b1);
                }
        }
        __syncthreads();
    }

#pragma unroll
    for (int mi = 0; mi < 2; mi++) {
#pragma unroll
        for (int h = 0; h < 2; h++) {
            long r = row0 + wm * 32 + mi * 16 + (lane >> 2) + h * 8;
#pragma unroll
            for (int ni = 0; ni < 8; ni++) {
                int cn = (int)col0 + wn * 64 + ni * 8 + (lane & 3) * 2;
                float v0 = acc[mi][ni][h * 2]     + bias[cn];
                float v1 = acc[mi][ni][h * 2 + 1] + bias[cn + 1];
                v0 = v0 / (1.0f + __expf(-v0));
                v1 = v1 / (1.0f + __expf(-v1));
                __nv_bfloat162 h2 = __float22bfloat162_rn(make_float2(v0, v1));
                *(uint32_t*)(Cb + r * ldcb + cn) = *reinterpret_cast<uint32_t*>(&h2);
            }
        }
    }
}

// ---------------------------------------------------------------------------
// G4: g = sigmoid(hb @ w2T^T + b2), CTA tile = 128 rows (64 b x 2 m) x 128 c.
// In-CTA reduction over b -> newmem direct (no gate buffer, no atomics).
// ---------------------------------------------------------------------------
__global__ void __launch_bounds__(256, 2)
gemm_g4(const __nv_bfloat16* __restrict__ A, const __nv_bfloat16* __restrict__ B,
        const float* __restrict__ bias,
        const float* __restrict__ mem, const float* __restrict__ xm,
        float* __restrict__ nm)
{
    extern __shared__ char dsm[];
    const uint32_t sbase = (smem_u32(dsm) + 1023) & ~1023u;
    const int tid = threadIdx.x;
    const int wid = tid >> 5, lane = tid & 31;
    const int wm = wid & 3;
    const int wn = wid >> 2;
    const int m0 = blockIdx.y * 2;
    const int col0 = blockIdx.x * 128;
    const int K = 1024;

    const uint32_t sA[2] = { sbase,         sbase + 32768 };
    const uint32_t sB[2] = { sbase + 16384, sbase + 49152 };

    float acc[2][8][4];
#pragma unroll
    for (int i = 0; i < 2; i++)
#pragma unroll
        for (int j = 0; j < 8; j++)
#pragma unroll
            for (int q = 0; q < 4; q++) acc[i][j][q] = 0.0f;

    const char* Ag = (const char*)A;
    const char* Bg = (const char*)(B + (long)col0 * K);
    const long rowb = (long)K * 2;
    const int lr = tid >> 3;
    const int lc = tid & 7;
    const int nchunks = K >> 6;

#pragma unroll
    for (int j = 0; j < 4; j++) {
        int i = lr + j * 32;
        long gr = ((long)(i & 63) << 10) + m0 + (i >> 6);
        uint32_t off = (uint32_t)(i * 128) + (uint32_t)((lc ^ (i & 7)) << 4);
        CP_ASYNC16(sA[0] + off, Ag + gr * rowb + lc * 16);
        CP_ASYNC16(sB[0] + off, Bg + (long)i * rowb + lc * 16);
    }
    CP_COMMIT();

    for (int it = 0; it < nchunks; it++) {
        const int b = it & 1;
        if (it + 1 < nchunks) {
            const long kb = (long)(it + 1) << 7;
#pragma unroll
            for (int j = 0; j < 4; j++) {
                int i = lr + j * 32;
                long gr = ((long)(i & 63) << 10) + m0 + (i >> 6);
                uint32_t off = (uint32_t)(i * 128) + (uint32_t)((lc ^ (i & 7)) << 4);
                CP_ASYNC16(sA[1 - b] + off, Ag + gr * rowb + kb + lc * 16);
                CP_ASYNC16(sB[1 - b] + off, Bg + (long)i * rowb + kb + lc * 16);
            }
            CP_COMMIT();
            CP_WAIT(1);
        } else {
            CP_WAIT(0);
        }
        __syncthreads();

#pragma unroll
        for (int ks = 0; ks < 4; ks++) {
            uint32_t af[2][4];
#pragma unroll
            for (int mi = 0; mi < 2; mi++) {
                int r = wm * 32 + mi * 16 + (lane & 15);
                int cch = ks * 2 + (lane >> 4);
                uint32_t addr = sA[b] + (uint32_t)(r * 128) + (uint32_t)((cch ^ (r & 7)) << 4);
                LDSM_X4(af[mi][0], af[mi][1], af[mi][2], af[mi][3], addr);
            }
            uint32_t bf[4][4];
#pragma unroll
            for (int nt = 0; nt < 4; nt++) {
                int r = wn * 64 + nt * 16 + (lane & 7) + ((lane >> 4) << 3);
                int cch = ks * 2 + ((lane >> 3) & 1);
                uint32_t addr = sB[b] + (uint32_t)(r * 128) + (uint32_t)((cch ^ (r & 7)) << 4);
                LDSM_X4(bf[nt][0], bf[nt][1], bf[nt][2], bf[nt][3], addr);
            }
#pragma unroll
            for (int mi = 0; mi < 2; mi++)
#pragma unroll
                for (int ni = 0; ni < 8; ni++) {
                    uint32_t b0 = bf[ni >> 1][(ni & 1) * 2];
                    uint32_t b1 = bf[ni >> 1][(ni & 1) * 2 + 1];
                    MMA16816(acc[mi][ni], af[mi][0], af[mi][1], af[mi][2], af[mi][3], b0, b1);
                }
        }
        __syncthreads();
    }

    // ---- epilogue: blend into padded smem (528B rows), reduce over b ----
#pragma unroll
    for (int mi = 0; mi < 2; mi++) {
#pragma unroll
        for (int h = 0; h < 2; h++) {
            int il = wm * 32 + mi * 16 + (lane >> 2) + h * 8;
            int bb = il & 63;
            int mloc = il >> 6;
#pragma unroll
            for (int ni = 0; ni < 8; ni++) {
                int cl = wn * 64 + ni * 8 + (lane & 3) * 2;
                int cn = col0 + cl;
                float v0 = acc[mi][ni][h * 2]     + bias[cn];
                float v1 = acc[mi][ni][h * 2 + 1] + bias[cn + 1];
                float g0 = 1.0f / (1.0f + __expf(-v0));
                float g1 = 1.0f / (1.0f + __expf(-v1));
                float mm0 = mem[(m0 + mloc) * 256 + cn];
                float mm1 = mem[(m0 + mloc) * 256 + cn + 1];
                float xv0 = xm[bb * 256 + cn];
                float xv1 = xm[bb * 256 + cn + 1];
                float o0 = fmaf(xv0 - mm0, g0, mm0) * (1.0f / 64.0f);
                float o1 = fmaf(xv1 - mm1, g1, mm1) * (1.0f / 64.0f);
                *(float2*)(dsm + (sbase - smem_u32(dsm)) + il * 528 + cl * 4) = make_float2(o0, o1);
            }
        }
    }
    __syncthreads();

    {
        int mloc = tid >> 7;
        int c = tid & 127;
        const char* sred = dsm + (sbase - smem_u32(dsm));
        float s = 0.0f;
#pragma unroll
        for (int k = 0; k < 64; k++) {
            int il = mloc * 64 + k;
            s += *(const float*)(sred + il * 528 + c * 4);
        }
        nm[(m0 + mloc) * 256 + col0 + c] = s;
    }
}

// ---------------------------------------------------------------------------
// merged weight conversions (memb + w1T + w2T)
// ---------------------------------------------------------------------------
__global__ void conv_all(const float* __restrict__ mem, const float* __restrict__ w1,
                         const float* __restrict__ w2,
                         __nv_bfloat16* __restrict__ memb, __nv_bfloat16* __restrict__ w1T,
                         __nv_bfloat16* __restrict__ w2T)
{
    int i = blockIdx.x * 256 + threadIdx.x;   // 0..524287
    {
        int k = i >> 10, n = i & 1023;
        w1T[n * 512 + k] = __float2bfloat16(w1[i]);
    }
    if (i < 262144) {
        memb[i] = __float2bfloat16(mem[i]);
        int f = i >> 8, c = i & 255;
        w2T[c * 1024 + f] = __float2bfloat16(w2[i]);
    }
}

// combine xmean partials (raw sums -> mean)
__global__ void xmean_comb(const float* __restrict__ xpart, float* __restrict__ xmn)
{
    int i = blockIdx.x * 256 + threadIdx.x;   // 0..16383
    int b = i >> 8, c = i & 255;
    float s = 0.0f;
#pragma unroll
    for (int k = 0; k < 8; k++) s += xpart[(b * 8 + k) * 256 + c];
    xmn[i] = s * (1.0f / 1024.0f);
}

// ---------------------------------------------------------------------------
extern "C" void kernel_launch(void* const* d_in, const int* in_sizes, int n_in,
                              void* d_out, int out_size)
{
    const float* x      = (const float*)d_in[0];
    const float* memory = (const float*)d_in[1];
    const float* w1     = (const float*)d_in[2];
    const float* b1     = (const float*)d_in[3];
    const float* w2     = (const float*)d_in[4];
    const float* b2     = (const float*)d_in[5];

    float* out    = (float*)d_out;
    float* cat    = out;               // [65536,512]
    float* newmem = out + 33554432ll;  // [1024,256]

    __nv_bfloat16 *catb, *hb, *memb, *w1T, *w2T;
    float *xp, *xmn;
    cudaGetSymbolAddress((void**)&catb, g_catb);
    cudaGetSymbolAddress((void**)&hb, g_hb);
    cudaGetSymbolAddress((void**)&memb, g_memb);
    cudaGetSymbolAddress((void**)&w1T, g_w1T);
    cudaGetSymbolAddress((void**)&w2T, g_w2T);
    cudaGetSymbolAddress((void**)&xp, g_xpart);
    cudaGetSymbolAddress((void**)&xmn, g_xmean);

    const int SMEM_G3 = 1024 + 65536;
    const int SMEM_G4 = 1024 + 128 * 528;
    const int SMEM_F  = 1024 + 3 * 65536 + 4096;   // guard + x + 2 mem + red buf
    cudaFuncSetAttribute(gemm_g3, cudaFuncAttributeMaxDynamicSharedMemorySize, SMEM_G3);
    cudaFuncSetAttribute(gemm_g4, cudaFuncAttributeMaxDynamicSharedMemorySize, SMEM_G4);
    cudaFuncSetAttribute(flash_attn, cudaFuncAttributeMaxDynamicSharedMemorySize, SMEM_F);

    // weight conversions
    conv_all<<<2048, 256>>>(memory, w1, w2, memb, w1T, w2T);

    // flash: x convert + cat0/catb0 + xmean partials + attention -> cat1/catb1
    flash_attn<<<512, 256, SMEM_F>>>(x, memb, cat, catb, xp);

    // combine xmean partials
    xmean_comb<<<64, 256>>>(xp, xmn);

    // G3: h = silu(catb @ w1T^T + b1) -> hb bf16 [65536,1024]
    gemm_g3<<<dim3(8, 512), 256, SMEM_G3>>>(catb, w1T, b1, hb, 512, 1024);

    // G4: g = sigmoid(hb @ w2T^T + b2) -> newmem (in-CTA b-reduction)
    gemm_g4<<<dim3(2, 512), 256, SMEM_G4>>>(hb, w2T, b2, memory, xmn, newmem);
}